// round 1
// baseline (speedup 1.0000x reference)
#include <cuda_runtime.h>
#include <cstdint>

// Problem constants
#define BB 8
#define CC 256
#define CI 128
#define NN 4096          // H*W
#define MM 1024          // (H/2)*(W/2)
#define BN_EPS 1e-5f

// ---------------------------------------------------------------------------
// Scratch (static __device__ allocations only — no runtime allocation allowed)
// ---------------------------------------------------------------------------
__device__ float d_CONV[(size_t)BB * 384 * NN];   // theta(0:128) | phi(128:256) | g(256:384), full-res
__device__ float d_PGP[(size_t)BB * 256 * MM];    // pooled: phi(0:128) | g(128:256)
__device__ float d_S[(size_t)BB * NN * MM];       // attention scores -> probs (in place)
__device__ float d_Y[(size_t)BB * CI * NN];       // attention output, [Ci, N] layout
__device__ float d_WY[(size_t)BB * CC * NN];      // W conv output (pre-BN)
__device__ float d_Wcat[384 * CC];                // stacked theta/phi/g weights
__device__ float d_bcat[384];
__device__ double d_sum[CC];
__device__ double d_sq[CC];
__device__ float d_scale[CC];
__device__ float d_shift[CC];

// ---------------------------------------------------------------------------
// Shared GEMM micro-kernel: 128x128 block tile, BK=16, 8x8 per-thread tile
// ---------------------------------------------------------------------------
__device__ __forceinline__ void gemm_core(const float (&As)[16][128],
                                          const float (&Bs)[16][128],
                                          float (&acc)[8][8], int tx, int ty) {
  __syncthreads();
#pragma unroll
  for (int k = 0; k < 16; k++) {
    float af[8], bf[8];
    *(float4*)&af[0] = *(const float4*)&As[k][ty * 8];
    *(float4*)&af[4] = *(const float4*)&As[k][ty * 8 + 4];
    *(float4*)&bf[0] = *(const float4*)&Bs[k][tx * 8];
    *(float4*)&bf[4] = *(const float4*)&Bs[k][tx * 8 + 4];
#pragma unroll
    for (int i = 0; i < 8; i++)
#pragma unroll
      for (int j = 0; j < 8; j++)
        acc[i][j] = fmaf(af[i], bf[j], acc[i][j]);
  }
  __syncthreads();
}

__device__ __forceinline__ void st_trans(float (&T)[16][128], int kq, int row, float4 v) {
  T[kq + 0][row] = v.x;
  T[kq + 1][row] = v.y;
  T[kq + 2][row] = v.z;
  T[kq + 3][row] = v.w;
}

// ---------------------------------------------------------------------------
// init: pack stacked weights/biases, zero BN accumulators
// ---------------------------------------------------------------------------
__global__ __launch_bounds__(256) void init_kernel(
    const float* __restrict__ tw, const float* __restrict__ tb,
    const float* __restrict__ pw, const float* __restrict__ pb,
    const float* __restrict__ gw, const float* __restrict__ gb) {
  int idx = blockIdx.x * 256 + threadIdx.x;
  if (idx < CC) { d_sum[idx] = 0.0; d_sq[idx] = 0.0; }
  if (idx < 384)
    d_bcat[idx] = (idx < 128) ? tb[idx] : (idx < 256) ? pb[idx - 128] : gb[idx - 256];
  if (idx < 384 * CC) {
    int r = idx >> 8, c = idx & 255;
    d_Wcat[idx] = (r < 128) ? tw[r * CC + c]
                : (r < 256) ? pw[(r - 128) * CC + c]
                            : gw[(r - 256) * CC + c];
  }
}

// ---------------------------------------------------------------------------
// conv: CONV[b] = Wcat[384,256] @ x_b[256,4096] + bcat  (grid: 32 x 3 x 8)
// ---------------------------------------------------------------------------
__global__ __launch_bounds__(256) void conv_kernel(const float* __restrict__ x) {
  const int b = blockIdx.z;
  const int m0 = blockIdx.y * 128;
  const int n0 = blockIdx.x * 128;
  const float* X = x + (size_t)b * CC * NN;
  float* Cout = d_CONV + (size_t)b * 384 * NN;
  __shared__ float As[16][128];
  __shared__ float Bs[16][128];
  float acc[8][8] = {};
  const int tid = threadIdx.x;
  const int tx = tid & 15, ty = tid >> 4;
  const int arow = tid >> 2;
  const int akq = (tid & 3) << 2;
  const int bk = tid >> 5;
  const int bn = (tid & 31) << 2;
  for (int k0 = 0; k0 < CC; k0 += 16) {
    float4 a0 = *(const float4*)&d_Wcat[(m0 + arow) * CC + k0 + akq];
    float4 a1 = *(const float4*)&d_Wcat[(m0 + arow + 64) * CC + k0 + akq];
    st_trans(As, akq, arow, a0);
    st_trans(As, akq, arow + 64, a1);
    *(float4*)&Bs[bk][bn]     = *(const float4*)&X[(size_t)(k0 + bk) * NN + n0 + bn];
    *(float4*)&Bs[bk + 8][bn] = *(const float4*)&X[(size_t)(k0 + bk + 8) * NN + n0 + bn];
    gemm_core(As, Bs, acc, tx, ty);
  }
#pragma unroll
  for (int i = 0; i < 8; i++) {
    int m = m0 + ty * 8 + i;
    float bias = d_bcat[m];
#pragma unroll
    for (int jq = 0; jq < 8; jq += 4) {
      float4 v;
      v.x = acc[i][jq] + bias;     v.y = acc[i][jq + 1] + bias;
      v.z = acc[i][jq + 2] + bias; v.w = acc[i][jq + 3] + bias;
      *(float4*)&Cout[(size_t)m * NN + n0 + tx * 8 + jq] = v;
    }
  }
}

// ---------------------------------------------------------------------------
// pool: 2x2 maxpool of phi, g -> d_PGP  (phi ch 0..127, g ch 128..255)
// ---------------------------------------------------------------------------
__global__ __launch_bounds__(256) void pool_kernel() {
  int idx = blockIdx.x * 256 + threadIdx.x;  // over 8*256*1024
  int m = idx & 1023;
  int c = (idx >> 10) & 255;
  int b = idx >> 18;
  int hp = m >> 5, wp = m & 31;
  const float* src = d_CONV + ((size_t)b * 384 + 128 + c) * NN + (hp * 2) * 64 + wp * 2;
  d_PGP[idx] = fmaxf(fmaxf(src[0], src[1]), fmaxf(src[64], src[65]));
}

// ---------------------------------------------------------------------------
// scores: S[b] = theta^T[4096,128] @ phi[128,1024]   (grid: 8 x 32 x 8)
// both operands are K-major -> fully coalesced direct tile loads
// ---------------------------------------------------------------------------
__global__ __launch_bounds__(256) void s_kernel() {
  const int b = blockIdx.z;
  const int n0 = blockIdx.y * 128;
  const int m0 = blockIdx.x * 128;
  const float* theta = d_CONV + (size_t)b * 384 * NN;  // rows 0..127
  const float* phi = d_PGP + (size_t)b * 256 * MM;     // rows 0..127
  __shared__ float As[16][128];  // [k][n]
  __shared__ float Bs[16][128];  // [k][m]
  float acc[8][8] = {};
  const int tid = threadIdx.x;
  const int tx = tid & 15, ty = tid >> 4;
  const int bk = tid >> 5;
  const int bn = (tid & 31) << 2;
  for (int k0 = 0; k0 < CI; k0 += 16) {
    *(float4*)&As[bk][bn]     = *(const float4*)&theta[(size_t)(k0 + bk) * NN + n0 + bn];
    *(float4*)&As[bk + 8][bn] = *(const float4*)&theta[(size_t)(k0 + bk + 8) * NN + n0 + bn];
    *(float4*)&Bs[bk][bn]     = *(const float4*)&phi[(size_t)(k0 + bk) * MM + m0 + bn];
    *(float4*)&Bs[bk + 8][bn] = *(const float4*)&phi[(size_t)(k0 + bk + 8) * MM + m0 + bn];
    gemm_core(As, Bs, acc, tx, ty);
  }
  float* Sb = d_S + (size_t)b * NN * MM;
#pragma unroll
  for (int i = 0; i < 8; i++) {
    int n = n0 + ty * 8 + i;
#pragma unroll
    for (int jq = 0; jq < 8; jq += 4)
      *(float4*)&Sb[(size_t)n * MM + m0 + tx * 8 + jq] = *(float4*)&acc[i][jq];
  }
}

// ---------------------------------------------------------------------------
// softmax over M=1024, one block of 128 threads per row (32768 rows)
// ---------------------------------------------------------------------------
__global__ __launch_bounds__(128) void softmax_kernel() {
  float* row = d_S + (size_t)blockIdx.x * MM;
  const int t = threadIdx.x;
  float4 v0 = *(float4*)&row[t * 8];
  float4 v1 = *(float4*)&row[t * 8 + 4];
  float mx = fmaxf(fmaxf(fmaxf(v0.x, v0.y), fmaxf(v0.z, v0.w)),
                   fmaxf(fmaxf(v1.x, v1.y), fmaxf(v1.z, v1.w)));
  __shared__ float red[4];
#pragma unroll
  for (int o = 16; o; o >>= 1) mx = fmaxf(mx, __shfl_xor_sync(0xffffffffu, mx, o));
  if ((t & 31) == 0) red[t >> 5] = mx;
  __syncthreads();
  mx = fmaxf(fmaxf(red[0], red[1]), fmaxf(red[2], red[3]));
  v0.x = __expf(v0.x - mx); v0.y = __expf(v0.y - mx);
  v0.z = __expf(v0.z - mx); v0.w = __expf(v0.w - mx);
  v1.x = __expf(v1.x - mx); v1.y = __expf(v1.y - mx);
  v1.z = __expf(v1.z - mx); v1.w = __expf(v1.w - mx);
  float s = v0.x + v0.y + v0.z + v0.w + v1.x + v1.y + v1.z + v1.w;
  __syncthreads();
#pragma unroll
  for (int o = 16; o; o >>= 1) s += __shfl_xor_sync(0xffffffffu, s, o);
  if ((t & 31) == 0) red[t >> 5] = s;
  __syncthreads();
  float inv = 1.0f / (red[0] + red[1] + red[2] + red[3]);
  v0.x *= inv; v0.y *= inv; v0.z *= inv; v0.w *= inv;
  v1.x *= inv; v1.y *= inv; v1.z *= inv; v1.w *= inv;
  *(float4*)&row[t * 8] = v0;
  *(float4*)&row[t * 8 + 4] = v1;
}

// ---------------------------------------------------------------------------
// y: Y[b][c,n] = sum_m g[c,m] * P[n,m]  (grid: 32 x 1 x 8), K = M = 1024
// both operands row-major over m -> transpose tile loads
// ---------------------------------------------------------------------------
__global__ __launch_bounds__(256) void y_kernel() {
  const int b = blockIdx.z;
  const int n0 = blockIdx.x * 128;
  const float* g = d_PGP + (size_t)b * 256 * MM + (size_t)128 * MM;  // [128, M]
  const float* Sb = d_S + (size_t)b * NN * MM;
  __shared__ float As[16][128];  // [k][c]
  __shared__ float Bs[16][128];  // [k][n]
  float acc[8][8] = {};
  const int tid = threadIdx.x;
  const int tx = tid & 15, ty = tid >> 4;
  const int arow = tid >> 2;
  const int akq = (tid & 3) << 2;
  for (int k0 = 0; k0 < MM; k0 += 16) {
    float4 a0 = *(const float4*)&g[(size_t)arow * MM + k0 + akq];
    float4 a1 = *(const float4*)&g[(size_t)(arow + 64) * MM + k0 + akq];
    st_trans(As, akq, arow, a0);
    st_trans(As, akq, arow + 64, a1);
    float4 c0 = *(const float4*)&Sb[(size_t)(n0 + arow) * MM + k0 + akq];
    float4 c1 = *(const float4*)&Sb[(size_t)(n0 + arow + 64) * MM + k0 + akq];
    st_trans(Bs, akq, arow, c0);
    st_trans(Bs, akq, arow + 64, c1);
    gemm_core(As, Bs, acc, tx, ty);
  }
#pragma unroll
  for (int i = 0; i < 8; i++) {
    int c = ty * 8 + i;
#pragma unroll
    for (int jq = 0; jq < 8; jq += 4)
      *(float4*)&d_Y[((size_t)b * CI + c) * NN + n0 + tx * 8 + jq] = *(float4*)&acc[i][jq];
  }
}

// ---------------------------------------------------------------------------
// W conv + BN statistics: WY[b][o,n] = W_w[o,:] @ Y[b][:,n] + W_b[o]
// grid: 32 x 2 x 8
// ---------------------------------------------------------------------------
__global__ __launch_bounds__(256) void wconv_kernel(const float* __restrict__ Ww,
                                                    const float* __restrict__ Wb) {
  const int b = blockIdx.z;
  const int o0 = blockIdx.y * 128;
  const int n0 = blockIdx.x * 128;
  const float* Y = d_Y + (size_t)b * CI * NN;
  __shared__ float As[16][128];
  __shared__ float Bs[16][128];
  __shared__ float s_sum[128];
  __shared__ float s_sq[128];
  float acc[8][8] = {};
  const int tid = threadIdx.x;
  const int tx = tid & 15, ty = tid >> 4;
  const int arow = tid >> 2;
  const int akq = (tid & 3) << 2;
  const int bk = tid >> 5;
  const int bn = (tid & 31) << 2;
  if (tid < 128) { s_sum[tid] = 0.f; s_sq[tid] = 0.f; }
  for (int k0 = 0; k0 < CI; k0 += 16) {
    float4 a0 = *(const float4*)&Ww[(o0 + arow) * CI + k0 + akq];
    float4 a1 = *(const float4*)&Ww[(o0 + arow + 64) * CI + k0 + akq];
    st_trans(As, akq, arow, a0);
    st_trans(As, akq, arow + 64, a1);
    *(float4*)&Bs[bk][bn]     = *(const float4*)&Y[(size_t)(k0 + bk) * NN + n0 + bn];
    *(float4*)&Bs[bk + 8][bn] = *(const float4*)&Y[(size_t)(k0 + bk + 8) * NN + n0 + bn];
    gemm_core(As, Bs, acc, tx, ty);
  }
  float* WYb = d_WY + (size_t)b * CC * NN;
#pragma unroll
  for (int i = 0; i < 8; i++) {
    int orow = ty * 8 + i;
    int o = o0 + orow;
    float bias = Wb[o];
    float ls = 0.f, lq = 0.f;
#pragma unroll
    for (int jq = 0; jq < 8; jq += 4) {
      float4 v;
      v.x = acc[i][jq] + bias;     v.y = acc[i][jq + 1] + bias;
      v.z = acc[i][jq + 2] + bias; v.w = acc[i][jq + 3] + bias;
      ls += v.x + v.y + v.z + v.w;
      lq += v.x * v.x + v.y * v.y + v.z * v.z + v.w * v.w;
      *(float4*)&WYb[(size_t)o * NN + n0 + tx * 8 + jq] = v;
    }
    atomicAdd(&s_sum[orow], ls);
    atomicAdd(&s_sq[orow], lq);
  }
  __syncthreads();
  if (tid < 128) {
    atomicAdd(&d_sum[o0 + tid], (double)s_sum[tid]);
    atomicAdd(&d_sq[o0 + tid], (double)s_sq[tid]);
  }
}

// ---------------------------------------------------------------------------
// BN finalize: per-channel scale/shift
// ---------------------------------------------------------------------------
__global__ void bnprep_kernel(const float* __restrict__ gamma,
                              const float* __restrict__ beta) {
  int o = threadIdx.x;  // 256 threads
  double cnt = (double)BB * (double)NN;
  double mean = d_sum[o] / cnt;
  double var = d_sq[o] / cnt - mean * mean;
  float sc = gamma[o] * rsqrtf((float)var + BN_EPS);
  d_scale[o] = sc;
  d_shift[o] = beta[o] - (float)mean * sc;
}

// ---------------------------------------------------------------------------
// final: out = WY*scale + shift + x   (vectorized float4)
// ---------------------------------------------------------------------------
__global__ __launch_bounds__(256) void final_kernel(const float* __restrict__ x,
                                                    float* __restrict__ out) {
  size_t i4 = (size_t)blockIdx.x * 256 + threadIdx.x;  // over 2,097,152 float4s
  int o = (int)((i4 >> 10) & 255);
  float sc = d_scale[o], sh = d_shift[o];
  float4 w = ((const float4*)d_WY)[i4];
  float4 xi = ((const float4*)x)[i4];
  float4 r;
  r.x = w.x * sc + sh + xi.x;
  r.y = w.y * sc + sh + xi.y;
  r.z = w.z * sc + sh + xi.z;
  r.w = w.w * sc + sh + xi.w;
  ((float4*)out)[i4] = r;
}

// ---------------------------------------------------------------------------
// launch
// ---------------------------------------------------------------------------
extern "C" void kernel_launch(void* const* d_in, const int* in_sizes, int n_in,
                              void* d_out, int out_size) {
  const float* x  = (const float*)d_in[0];
  const float* tw = (const float*)d_in[1];
  const float* tb = (const float*)d_in[2];
  const float* pw = (const float*)d_in[3];
  const float* pb = (const float*)d_in[4];
  const float* gw = (const float*)d_in[5];
  const float* gb = (const float*)d_in[6];
  const float* Ww = (const float*)d_in[7];
  const float* Wb = (const float*)d_in[8];
  const float* bg = (const float*)d_in[9];
  const float* bb = (const float*)d_in[10];
  float* out = (float*)d_out;

  init_kernel<<<384, 256>>>(tw, tb, pw, pb, gw, gb);
  conv_kernel<<<dim3(32, 3, BB), 256>>>(x);
  pool_kernel<<<(BB * 256 * MM) / 256, 256>>>();
  s_kernel<<<dim3(MM / 128, NN / 128, BB), 256>>>();
  softmax_kernel<<<BB * NN, 128>>>();
  y_kernel<<<dim3(NN / 128, 1, BB), 256>>>();
  wconv_kernel<<<dim3(NN / 128, 2, BB), 256>>>(Ww, Wb);
  bnprep_kernel<<<1, 256>>>(bg, bb);
  final_kernel<<<(BB * CC * NN / 4) / 256, 256>>>(x, out);
}

// round 7
// speedup vs baseline: 1.3284x; 1.3284x over previous
#include <cuda_runtime.h>
#include <cuda_bf16.h>
#include <cstdint>

// Problem constants
#define BB 8
#define CC 256
#define CI 128
#define NN 4096          // H*W
#define MM 1024          // (H/2)*(W/2)
#define BN_EPS 1e-5f

// ---------------------------------------------------------------------------
// Scratch (static __device__ allocations only)
// ---------------------------------------------------------------------------
__device__ float d_CONV[(size_t)BB * 384 * NN];   // theta(0:128)|phi(128:256)|g(256:384)
__device__ float d_S[(size_t)BB * NN * MM];       // raw attention scores [b][q][m]
__device__ float d_Y[(size_t)BB * CI * NN];       // attention output, [c][n]
__device__ float d_WY[(size_t)BB * CC * NN];      // W conv output (pre-BN)
__device__ float d_Wcat[384 * CC];
__device__ float d_bcat[384];
__device__ double d_sum[CC];
__device__ double d_sq[CC];
__device__ float d_scale[CC];
__device__ float d_shift[CC];
// bf16 hi/lo split operands for tensor-core GEMMs
__device__ __nv_bfloat16 d_Th[(size_t)BB * NN * CI];   // theta^T [b][n][ci]
__device__ __nv_bfloat16 d_Tl[(size_t)BB * NN * CI];
__device__ __nv_bfloat16 d_PHh[(size_t)BB * MM * CI];  // pooled phi [b][m][ci]
__device__ __nv_bfloat16 d_PHl[(size_t)BB * MM * CI];
__device__ __nv_bfloat16 d_Gh[(size_t)BB * CI * MM];   // pooled g [b][c][m]
__device__ __nv_bfloat16 d_Gl[(size_t)BB * CI * MM];
__device__ __nv_bfloat16 d_Ph[(size_t)BB * NN * MM];   // probs [b][q][m]
__device__ __nv_bfloat16 d_Pl[(size_t)BB * NN * MM];

// ---------------------------------------------------------------------------
// mma.sync helpers (baseline PTX, works on plain sm_103 target)
// ---------------------------------------------------------------------------
__device__ __forceinline__ uint32_t smem_u32(const void* p) {
  uint32_t a;
  asm("{ .reg .u64 t; cvta.to.shared.u64 t, %1; cvt.u32.u64 %0, t; }" : "=r"(a) : "l"(p));
  return a;
}
__device__ __forceinline__ void ldm_x4(uint32_t* r, uint32_t addr) {
  asm volatile("ldmatrix.sync.aligned.m8n8.x4.shared.b16 {%0,%1,%2,%3}, [%4];"
               : "=r"(r[0]), "=r"(r[1]), "=r"(r[2]), "=r"(r[3]) : "r"(addr));
}
__device__ __forceinline__ void mma_bf16(float* c, const uint32_t* a, uint32_t b0, uint32_t b1) {
  asm volatile(
      "mma.sync.aligned.m16n8k16.row.col.f32.bf16.bf16.f32 "
      "{%0,%1,%2,%3}, {%4,%5,%6,%7}, {%8,%9}, {%0,%1,%2,%3};"
      : "+f"(c[0]), "+f"(c[1]), "+f"(c[2]), "+f"(c[3])
      : "r"(a[0]), "r"(a[1]), "r"(a[2]), "r"(a[3]), "r"(b0), "r"(b1));
}

// smem tile: 128 rows x 64 bf16, padded row stride 72 elems (272B -> ldmatrix
// 8-address phases hit disjoint bank quads: 272 % 128 = 16B shift per row).
#define TPAD 72
#define TILE_ELEMS (128 * TPAD)

__device__ __forceinline__ void load_tile(__nv_bfloat16* s, const __nv_bfloat16* g,
                                          int gstride, int tid) {
#pragma unroll
  for (int i = 0; i < 4; i++) {
    int idx = tid + i * 256;
    int row = idx >> 3, c4 = idx & 7;
    *(uint4*)&s[row * TPAD + c4 * 8] = *(const uint4*)&g[(size_t)row * gstride + c4 * 8];
  }
}

// Warp-level 128x128 GEMM body over one 64-wide k-chunk already in smem.
// A rows = M (warp m = wm*32), B rows = N (warp n = wn*64). Hi/lo split: 3 mma terms.
__device__ __forceinline__ void chunk_mma(uint32_t sAh, uint32_t sAl, uint32_t sBh,
                                          uint32_t sBl, int wm, int wn, int lane,
                                          float (&C)[2][8][4]) {
  const int ar = wm * 32 + (lane & 15);
  const int ac = (lane >> 4) * 8;
  const int bg = lane >> 3;
  const int br = wn * 64 + ((bg & 2) << 2) + (lane & 7);
  const int bc = (bg & 1) << 3;
#pragma unroll
  for (int kk = 0; kk < 4; kk++) {
    uint32_t Ah[2][4], Al[2][4], Bh[4][4], Bl[4][4];
    uint32_t aoff = ((ar) * TPAD + kk * 16 + ac) * 2;
    ldm_x4(Ah[0], sAh + aoff);
    ldm_x4(Ah[1], sAh + aoff + 16 * TPAD * 2);
    ldm_x4(Al[0], sAl + aoff);
    ldm_x4(Al[1], sAl + aoff + 16 * TPAD * 2);
#pragma unroll
    for (int p = 0; p < 4; p++) {
      uint32_t boff = ((br + p * 16) * TPAD + kk * 16 + bc) * 2;
      ldm_x4(Bh[p], sBh + boff);
      ldm_x4(Bl[p], sBl + boff);
    }
#pragma unroll
    for (int mi = 0; mi < 2; mi++)
#pragma unroll
      for (int p = 0; p < 4; p++)
#pragma unroll
        for (int h = 0; h < 2; h++) {
          float* acc = C[mi][p * 2 + h];
          mma_bf16(acc, Ah[mi], Bh[p][h * 2], Bh[p][h * 2 + 1]);
          mma_bf16(acc, Ah[mi], Bl[p][h * 2], Bl[p][h * 2 + 1]);
          mma_bf16(acc, Al[mi], Bh[p][h * 2], Bh[p][h * 2 + 1]);
        }
  }
}

#define DSMEM_BYTES (4 * TILE_ELEMS * 2)  // 73728

// ---------------------------------------------------------------------------
// SIMT GEMM micro-kernel (conv / wconv)
// ---------------------------------------------------------------------------
__device__ __forceinline__ void gemm_core(const float (&As)[16][128],
                                          const float (&Bs)[16][128],
                                          float (&acc)[8][8], int tx, int ty) {
  __syncthreads();
#pragma unroll
  for (int k = 0; k < 16; k++) {
    float af[8], bf[8];
    *(float4*)&af[0] = *(const float4*)&As[k][ty * 8];
    *(float4*)&af[4] = *(const float4*)&As[k][ty * 8 + 4];
    *(float4*)&bf[0] = *(const float4*)&Bs[k][tx * 8];
    *(float4*)&bf[4] = *(const float4*)&Bs[k][tx * 8 + 4];
#pragma unroll
    for (int i = 0; i < 8; i++)
#pragma unroll
      for (int j = 0; j < 8; j++)
        acc[i][j] = fmaf(af[i], bf[j], acc[i][j]);
  }
  __syncthreads();
}
__device__ __forceinline__ void st_trans(float (&T)[16][128], int kq, int row, float4 v) {
  T[kq + 0][row] = v.x;
  T[kq + 1][row] = v.y;
  T[kq + 2][row] = v.z;
  T[kq + 3][row] = v.w;
}

// ---------------------------------------------------------------------------
// init
// ---------------------------------------------------------------------------
__global__ __launch_bounds__(256) void init_kernel(
    const float* __restrict__ tw, const float* __restrict__ tb,
    const float* __restrict__ pw, const float* __restrict__ pb,
    const float* __restrict__ gw, const float* __restrict__ gb) {
  int idx = blockIdx.x * 256 + threadIdx.x;
  if (idx < CC) { d_sum[idx] = 0.0; d_sq[idx] = 0.0; }
  if (idx < 384)
    d_bcat[idx] = (idx < 128) ? tb[idx] : (idx < 256) ? pb[idx - 128] : gb[idx - 256];
  if (idx < 384 * CC) {
    int r = idx >> 8, c = idx & 255;
    d_Wcat[idx] = (r < 128) ? tw[r * CC + c]
                : (r < 256) ? pw[(r - 128) * CC + c]
                            : gw[(r - 256) * CC + c];
  }
}

// ---------------------------------------------------------------------------
// conv: CONV[b] = Wcat[384,256] @ x_b[256,4096] + bcat  (grid: 32 x 3 x 8)
// ---------------------------------------------------------------------------
__global__ __launch_bounds__(256) void conv_kernel(const float* __restrict__ x) {
  const int b = blockIdx.z;
  const int m0 = blockIdx.y * 128;
  const int n0 = blockIdx.x * 128;
  const float* X = x + (size_t)b * CC * NN;
  float* Cout = d_CONV + (size_t)b * 384 * NN;
  __shared__ float As[16][128];
  __shared__ float Bs[16][128];
  float acc[8][8] = {};
  const int tid = threadIdx.x;
  const int tx = tid & 15, ty = tid >> 4;
  const int arow = tid >> 2;
  const int akq = (tid & 3) << 2;
  const int bk = tid >> 5;
  const int bn = (tid & 31) << 2;
  for (int k0 = 0; k0 < CC; k0 += 16) {
    float4 a0 = *(const float4*)&d_Wcat[(m0 + arow) * CC + k0 + akq];
    float4 a1 = *(const float4*)&d_Wcat[(m0 + arow + 64) * CC + k0 + akq];
    st_trans(As, akq, arow, a0);
    st_trans(As, akq, arow + 64, a1);
    *(float4*)&Bs[bk][bn]     = *(const float4*)&X[(size_t)(k0 + bk) * NN + n0 + bn];
    *(float4*)&Bs[bk + 8][bn] = *(const float4*)&X[(size_t)(k0 + bk + 8) * NN + n0 + bn];
    gemm_core(As, Bs, acc, tx, ty);
  }
#pragma unroll
  for (int i = 0; i < 8; i++) {
    int m = m0 + ty * 8 + i;
    float bias = d_bcat[m];
#pragma unroll
    for (int jq = 0; jq < 8; jq += 4) {
      float4 v;
      v.x = acc[i][jq] + bias;     v.y = acc[i][jq + 1] + bias;
      v.z = acc[i][jq + 2] + bias; v.w = acc[i][jq + 3] + bias;
      *(float4*)&Cout[(size_t)m * NN + n0 + tx * 8 + jq] = v;
    }
  }
}

// ---------------------------------------------------------------------------
// pool + bf16 split
// ---------------------------------------------------------------------------
__global__ __launch_bounds__(256) void pool_split_kernel() {
  int idx = blockIdx.x * 256 + threadIdx.x;  // over 8*128*1024
  int m = idx & 1023;
  int c = (idx >> 10) & 127;
  int b = idx >> 17;
  int hp = m >> 5, wp = m & 31;
  const float* ps = d_CONV + ((size_t)b * 384 + 128 + c) * NN + hp * 128 + wp * 2;
  float vp = fmaxf(fmaxf(ps[0], ps[1]), fmaxf(ps[64], ps[65]));
  const float* gs = d_CONV + ((size_t)b * 384 + 256 + c) * NN + hp * 128 + wp * 2;
  float vg = fmaxf(fmaxf(gs[0], gs[1]), fmaxf(gs[64], gs[65]));
  size_t po = ((size_t)b * MM + m) * CI + c;
  __nv_bfloat16 h = __float2bfloat16_rn(vp);
  d_PHh[po] = h;
  d_PHl[po] = __float2bfloat16_rn(vp - __bfloat162float(h));
  size_t go = ((size_t)b * CI + c) * MM + m;
  h = __float2bfloat16_rn(vg);
  d_Gh[go] = h;
  d_Gl[go] = __float2bfloat16_rn(vg - __bfloat162float(h));
}

// ---------------------------------------------------------------------------
// theta transpose + split: d_CONV[ci][n] -> d_Th/d_Tl [b][n][ci]
// ---------------------------------------------------------------------------
__global__ void theta_t_kernel() {  // block (32,32), grid (128,4,8)
  __shared__ float t[32][33];
  int b = blockIdx.z, c0 = blockIdx.y * 32, n0 = blockIdx.x * 32;
  int tx = threadIdx.x, ty = threadIdx.y;
  t[ty][tx] = d_CONV[((size_t)b * 384 + c0 + ty) * NN + n0 + tx];
  __syncthreads();
  float v = t[tx][ty];
  size_t o = ((size_t)b * NN + n0 + ty) * CI + c0 + tx;
  __nv_bfloat16 h = __float2bfloat16_rn(v);
  d_Th[o] = h;
  d_Tl[o] = __float2bfloat16_rn(v - __bfloat162float(h));
}

// ---------------------------------------------------------------------------
// s_mma: S[b][q][m] = theta^T phi, hi/lo split HMMA
// A = theta^T tile (rows q), B = phi tile (rows m). grid: (8 m, 32 q, 8 b)
// ---------------------------------------------------------------------------
__global__ __launch_bounds__(256) void s_mma_kernel() {
  extern __shared__ __align__(16) __nv_bfloat16 dsm[];
  __nv_bfloat16* Ah = dsm;
  __nv_bfloat16* Al = dsm + TILE_ELEMS;
  __nv_bfloat16* Bh = dsm + 2 * TILE_ELEMS;
  __nv_bfloat16* Bl = dsm + 3 * TILE_ELEMS;
  const int tid = threadIdx.x, wid = tid >> 5, lane = tid & 31;
  const int b = blockIdx.z, q0 = blockIdx.y * 128, m0 = blockIdx.x * 128;
  const int wm = wid >> 1, wn = wid & 1;
  const uint32_t sAh = smem_u32(Ah), sAl = smem_u32(Al);
  const uint32_t sBh = smem_u32(Bh), sBl = smem_u32(Bl);
  const __nv_bfloat16* gAh = d_Th + ((size_t)b * NN + q0) * CI;
  const __nv_bfloat16* gAl = d_Tl + ((size_t)b * NN + q0) * CI;
  const __nv_bfloat16* gBh = d_PHh + ((size_t)b * MM + m0) * CI;
  const __nv_bfloat16* gBl = d_PHl + ((size_t)b * MM + m0) * CI;
  float C[2][8][4] = {};
#pragma unroll
  for (int k0 = 0; k0 < CI; k0 += 64) {
    load_tile(Ah, gAh + k0, CI, tid);
    load_tile(Al, gAl + k0, CI, tid);
    load_tile(Bh, gBh + k0, CI, tid);
    load_tile(Bl, gBl + k0, CI, tid);
    __syncthreads();
    chunk_mma(sAh, sAl, sBh, sBl, wm, wn, lane, C);
    __syncthreads();
  }
  float* Sb = d_S + (size_t)b * NN * MM;
  const int qbase = q0 + wm * 32 + (lane >> 2);
  const int mbase = m0 + wn * 64 + (lane & 3) * 2;
#pragma unroll
  for (int mi = 0; mi < 2; mi++)
#pragma unroll
    for (int nj = 0; nj < 8; nj++) {
      int q = qbase + mi * 16;
      int m = mbase + nj * 8;
      *(float2*)&Sb[(size_t)q * MM + m] = make_float2(C[mi][nj][0], C[mi][nj][1]);
      *(float2*)&Sb[(size_t)(q + 8) * MM + m] = make_float2(C[mi][nj][2], C[mi][nj][3]);
    }
}

// ---------------------------------------------------------------------------
// softmax over M=1024, writes hi/lo bf16 probabilities
// ---------------------------------------------------------------------------
__global__ __launch_bounds__(128) void softmax_kernel() {
  const float* row = d_S + (size_t)blockIdx.x * MM;
  const int t = threadIdx.x;
  float4 v0 = *(const float4*)&row[t * 8];
  float4 v1 = *(const float4*)&row[t * 8 + 4];
  float mx = fmaxf(fmaxf(fmaxf(v0.x, v0.y), fmaxf(v0.z, v0.w)),
                   fmaxf(fmaxf(v1.x, v1.y), fmaxf(v1.z, v1.w)));
  __shared__ float red[4];
#pragma unroll
  for (int o = 16; o; o >>= 1) mx = fmaxf(mx, __shfl_xor_sync(0xffffffffu, mx, o));
  if ((t & 31) == 0) red[t >> 5] = mx;
  __syncthreads();
  mx = fmaxf(fmaxf(red[0], red[1]), fmaxf(red[2], red[3]));
  v0.x = __expf(v0.x - mx); v0.y = __expf(v0.y - mx);
  v0.z = __expf(v0.z - mx); v0.w = __expf(v0.w - mx);
  v1.x = __expf(v1.x - mx); v1.y = __expf(v1.y - mx);
  v1.z = __expf(v1.z - mx); v1.w = __expf(v1.w - mx);
  float s = v0.x + v0.y + v0.z + v0.w + v1.x + v1.y + v1.z + v1.w;
  __syncthreads();
#pragma unroll
  for (int o = 16; o; o >>= 1) s += __shfl_xor_sync(0xffffffffu, s, o);
  if ((t & 31) == 0) red[t >> 5] = s;
  __syncthreads();
  float inv = 1.0f / (red[0] + red[1] + red[2] + red[3]);
  float p[8] = {v0.x * inv, v0.y * inv, v0.z * inv, v0.w * inv,
                v1.x * inv, v1.y * inv, v1.z * inv, v1.w * inv};
  size_t base = (size_t)blockIdx.x * MM + t * 8;
  __nv_bfloat16 hbuf[8], lbuf[8];
#pragma unroll
  for (int j = 0; j < 8; j++) {
    __nv_bfloat16 h = __float2bfloat16_rn(p[j]);
    hbuf[j] = h;
    lbuf[j] = __float2bfloat16_rn(p[j] - __bfloat162float(h));
  }
  *(uint4*)&d_Ph[base] = *(uint4*)hbuf;
  *(uint4*)&d_Pl[base] = *(uint4*)lbuf;
}

// ---------------------------------------------------------------------------
// y_mma: Y[b][c][q] = sum_m g[c][m] P[q][m], hi/lo split HMMA
// A = g tile (rows c, all 128), B = P tile (rows q). K=1024. grid: (32 q, 1, 8 b)
// ---------------------------------------------------------------------------
__global__ __launch_bounds__(256) void y_mma_kernel() {
  extern __shared__ __align__(16) __nv_bfloat16 dsm[];
  __nv_bfloat16* Ah = dsm;
  __nv_bfloat16* Al = dsm + TILE_ELEMS;
  __nv_bfloat16* Bh = dsm + 2 * TILE_ELEMS;
  __nv_bfloat16* Bl = dsm + 3 * TILE_ELEMS;
  const int tid = threadIdx.x, wid = tid >> 5, lane = tid & 31;
  const int b = blockIdx.z, q0 = blockIdx.x * 128;
  const int wm = wid >> 1, wn = wid & 1;
  const uint32_t sAh = smem_u32(Ah), sAl = smem_u32(Al);
  const uint32_t sBh = smem_u32(Bh), sBl = smem_u32(Bl);
  const __nv_bfloat16* gAh = d_Gh + (size_t)b * CI * MM;
  const __nv_bfloat16* gAl = d_Gl + (size_t)b * CI * MM;
  const __nv_bfloat16* gBh = d_Ph + ((size_t)b * NN + q0) * MM;
  const __nv_bfloat16* gBl = d_Pl + ((size_t)b * NN + q0) * MM;
  float C[2][8][4] = {};
  for (int k0 = 0; k0 < MM; k0 += 64) {
    load_tile(Ah, gAh + k0, MM, tid);
    load_tile(Al, gAl + k0, MM, tid);
    load_tile(Bh, gBh + k0, MM, tid);
    load_tile(Bl, gBl + k0, MM, tid);
    __syncthreads();
    chunk_mma(sAh, sAl, sBh, sBl, wm, wn, lane, C);
    __syncthreads();
  }
  const int cbase = wm * 32 + (lane >> 2);
  const int qbase = q0 + wn * 64 + (lane & 3) * 2;
#pragma unroll
  for (int mi = 0; mi < 2; mi++)
#pragma unroll
    for (int nj = 0; nj < 8; nj++) {
      int c = cbase + mi * 16;
      int q = qbase + nj * 8;
      *(float2*)&d_Y[((size_t)b * CI + c) * NN + q] = make_float2(C[mi][nj][0], C[mi][nj][1]);
      *(float2*)&d_Y[((size_t)b * CI + c + 8) * NN + q] = make_float2(C[mi][nj][2], C[mi][nj][3]);
    }
}

// ---------------------------------------------------------------------------
// W conv + BN statistics (SIMT): grid 32 x 2 x 8
// ---------------------------------------------------------------------------
__global__ __launch_bounds__(256) void wconv_kernel(const float* __restrict__ Ww,
                                                    const float* __restrict__ Wb) {
  const int b = blockIdx.z;
  const int o0 = blockIdx.y * 128;
  const int n0 = blockIdx.x * 128;
  const float* Y = d_Y + (size_t)b * CI * NN;
  __shared__ float As[16][128];
  __shared__ float Bs[16][128];
  __shared__ float s_sum[128];
  __shared__ float s_sq[128];
  float acc[8][8] = {};
  const int tid = threadIdx.x;
  const int tx = tid & 15, ty = tid >> 4;
  const int arow = tid >> 2;
  const int akq = (tid & 3) << 2;
  const int bk = tid >> 5;
  const int bn = (tid & 31) << 2;
  if (tid < 128) { s_sum[tid] = 0.f; s_sq[tid] = 0.f; }
  for (int k0 = 0; k0 < CI; k0 += 16) {
    float4 a0 = *(const float4*)&Ww[(o0 + arow) * CI + k0 + akq];
    float4 a1 = *(const float4*)&Ww[(o0 + arow + 64) * CI + k0 + akq];
    st_trans(As, akq, arow, a0);
    st_trans(As, akq, arow + 64, a1);
    *(float4*)&Bs[bk][bn]     = *(const float4*)&Y[(size_t)(k0 + bk) * NN + n0 + bn];
    *(float4*)&Bs[bk + 8][bn] = *(const float4*)&Y[(size_t)(k0 + bk + 8) * NN + n0 + bn];
    gemm_core(As, Bs, acc, tx, ty);
  }
  float* WYb = d_WY + (size_t)b * CC * NN;
#pragma unroll
  for (int i = 0; i < 8; i++) {
    int orow = ty * 8 + i;
    int o = o0 + orow;
    float bias = Wb[o];
    float ls = 0.f, lq = 0.f;
#pragma unroll
    for (int jq = 0; jq < 8; jq += 4) {
      float4 v;
      v.x = acc[i][jq] + bias;     v.y = acc[i][jq + 1] + bias;
      v.z = acc[i][jq + 2] + bias; v.w = acc[i][jq + 3] + bias;
      ls += v.x + v.y + v.z + v.w;
      lq += v.x * v.x + v.y * v.y + v.z * v.z + v.w * v.w;
      *(float4*)&WYb[(size_t)o * NN + n0 + tx * 8 + jq] = v;
    }
    atomicAdd(&s_sum[orow], ls);
    atomicAdd(&s_sq[orow], lq);
  }
  __syncthreads();
  if (tid < 128) {
    atomicAdd(&d_sum[o0 + tid], (double)s_sum[tid]);
    atomicAdd(&d_sq[o0 + tid], (double)s_sq[tid]);
  }
}

// ---------------------------------------------------------------------------
// BN finalize
// ---------------------------------------------------------------------------
__global__ void bnprep_kernel(const float* __restrict__ gamma,
                              const float* __restrict__ beta) {
  int o = threadIdx.x;
  double cnt = (double)BB * (double)NN;
  double mean = d_sum[o] / cnt;
  double var = d_sq[o] / cnt - mean * mean;
  float sc = gamma[o] * rsqrtf((float)var + BN_EPS);
  d_scale[o] = sc;
  d_shift[o] = beta[o] - (float)mean * sc;
}

// ---------------------------------------------------------------------------
// final: out = WY*scale + shift + x
// ---------------------------------------------------------------------------
__global__ __launch_bounds__(256) void final_kernel(const float* __restrict__ x,
                                                    float* __restrict__ out) {
  size_t i4 = (size_t)blockIdx.x * 256 + threadIdx.x;
  int o = (int)((i4 >> 10) & 255);
  float sc = d_scale[o], sh = d_shift[o];
  float4 w = ((const float4*)d_WY)[i4];
  float4 xi = ((const float4*)x)[i4];
  float4 r;
  r.x = w.x * sc + sh + xi.x;
  r.y = w.y * sc + sh + xi.y;
  r.z = w.z * sc + sh + xi.z;
  r.w = w.w * sc + sh + xi.w;
  ((float4*)out)[i4] = r;
}

// ---------------------------------------------------------------------------
// launch
// ---------------------------------------------------------------------------
extern "C" void kernel_launch(void* const* d_in, const int* in_sizes, int n_in,
                              void* d_out, int out_size) {
  const float* x  = (const float*)d_in[0];
  const float* tw = (const float*)d_in[1];
  const float* tb = (const float*)d_in[2];
  const float* pw = (const float*)d_in[3];
  const float* pb = (const float*)d_in[4];
  const float* gw = (const float*)d_in[5];
  const float* gb = (const float*)d_in[6];
  const float* Ww = (const float*)d_in[7];
  const float* Wb = (const float*)d_in[8];
  const float* bg = (const float*)d_in[9];
  const float* bb = (const float*)d_in[10];
  float* out = (float*)d_out;

  cudaFuncSetAttribute(s_mma_kernel, cudaFuncAttributeMaxDynamicSharedMemorySize, DSMEM_BYTES);
  cudaFuncSetAttribute(y_mma_kernel, cudaFuncAttributeMaxDynamicSharedMemorySize, DSMEM_BYTES);

  init_kernel<<<384, 256>>>(tw, tb, pw, pb, gw, gb);
  conv_kernel<<<dim3(32, 3, BB), 256>>>(x);
  pool_split_kernel<<<(BB * 128 * MM) / 256, 256>>>();
  theta_t_kernel<<<dim3(128, 4, BB), dim3(32, 32)>>>();
  s_mma_kernel<<<dim3(8, 32, BB), 256, DSMEM_BYTES>>>();
  softmax_kernel<<<BB * NN, 128>>>();
  y_mma_kernel<<<dim3(32, 1, BB), 256, DSMEM_BYTES>>>();
  wconv_kernel<<<dim3(32, 2, BB), 256>>>(Ww, Wb);
  bnprep_kernel<<<1, 256>>>(bg, bb);
  final_kernel<<<(BB * CC * NN / 4) / 256, 256>>>(x, out);
}